// round 1
// baseline (speedup 1.0000x reference)
#include <cuda_runtime.h>
#include <math.h>

#define BB 16
#define L  2048
#define D  128
#define DV 128
#define EPSV 1e-12f

// ---- stats scratch (device globals; no allocation allowed) ----
__device__ float g_rm[BB * L];        // row max
__device__ float g_rdi[BB * L];       // 1/(row denom + eps)
__device__ float g_cm[BB * L];        // col max
__device__ float g_cdi[BB * L];       // 1/(col denom + eps)
__device__ float g_cpm[8 * BB * L];   // col partial max  [ic][b*L + j]
__device__ float g_cps[8 * BB * L];   // col partial sum

// ============================================================
// K1: S[b,i,j] = sum_d q[b,i,d] * k[b,j,d]   (NT GEMM, fp32 SIMT)
// grid (L/128, L/128, B), block 256, 128x128 tile, 8x8 per thread
// ============================================================
__global__ __launch_bounds__(256) void k_gemm_qk(
    const float* __restrict__ q, const float* __restrict__ kmat,
    float* __restrict__ S)
{
    __shared__ float Qs[16][132];
    __shared__ float Ks[16][132];
    const int b  = blockIdx.z;
    const int i0 = blockIdx.y * 128;
    const int j0 = blockIdx.x * 128;
    const float* qb = q    + (size_t)b * L * D;
    const float* kb = kmat + (size_t)b * L * D;
    const int tid = threadIdx.x;
    const int tx = tid & 15, ty = tid >> 4;

    float acc[8][8];
#pragma unroll
    for (int m = 0; m < 8; m++)
#pragma unroll
        for (int n = 0; n < 8; n++) acc[m][n] = 0.f;

    for (int d0 = 0; d0 < D; d0 += 16) {
#pragma unroll
        for (int r = 0; r < 2; r++) {
            int f   = tid + r * 256;      // float4 index into 128x16 tile
            int row = f >> 2;
            int c4  = f & 3;
            float4 a4 = *reinterpret_cast<const float4*>(qb + (size_t)(i0 + row) * D + d0 + c4 * 4);
            Qs[c4 * 4 + 0][row] = a4.x; Qs[c4 * 4 + 1][row] = a4.y;
            Qs[c4 * 4 + 2][row] = a4.z; Qs[c4 * 4 + 3][row] = a4.w;
            float4 b4 = *reinterpret_cast<const float4*>(kb + (size_t)(j0 + row) * D + d0 + c4 * 4);
            Ks[c4 * 4 + 0][row] = b4.x; Ks[c4 * 4 + 1][row] = b4.y;
            Ks[c4 * 4 + 2][row] = b4.z; Ks[c4 * 4 + 3][row] = b4.w;
        }
        __syncthreads();
#pragma unroll
        for (int kk = 0; kk < 16; kk++) {
            float a[8], bv[8];
            *reinterpret_cast<float4*>(a)      = *reinterpret_cast<const float4*>(&Qs[kk][ty * 8]);
            *reinterpret_cast<float4*>(a + 4)  = *reinterpret_cast<const float4*>(&Qs[kk][ty * 8 + 4]);
            *reinterpret_cast<float4*>(bv)     = *reinterpret_cast<const float4*>(&Ks[kk][tx * 8]);
            *reinterpret_cast<float4*>(bv + 4) = *reinterpret_cast<const float4*>(&Ks[kk][tx * 8 + 4]);
#pragma unroll
            for (int m = 0; m < 8; m++)
#pragma unroll
                for (int n = 0; n < 8; n++) acc[m][n] += a[m] * bv[n];
        }
        __syncthreads();
    }

    float* Sb = S + ((size_t)b * L + i0) * L + j0;
#pragma unroll
    for (int m = 0; m < 8; m++) {
        float* row = Sb + (size_t)(ty * 8 + m) * L + tx * 8;
        *reinterpret_cast<float4*>(row)     = make_float4(acc[m][0], acc[m][1], acc[m][2], acc[m][3]);
        *reinterpret_cast<float4*>(row + 4) = make_float4(acc[m][4], acc[m][5], acc[m][6], acc[m][7]);
    }
}

// ============================================================
// K2: per-row online max + masked-exp sum.  grid B*L, block 256.
// ============================================================
__global__ __launch_bounds__(256) void k_rowstats(
    const float* __restrict__ S, const float* __restrict__ M)
{
    __shared__ float sm[256], ss[256];
    const size_t bi = blockIdx.x;
    const float* Sr = S + bi * L;
    const float* Mr = M + bi * L;
    const int tid = threadIdx.x;
    float m = -3.0e38f, s = 0.f;
#pragma unroll
    for (int it = 0; it < L / 256; it++) {
        int j = it * 256 + tid;
        float x  = Sr[j];
        float mk = Mr[j];
        float nm = fmaxf(m, x);
        s = s * __expf(m - nm) + mk * __expf(x - nm);
        m = nm;
    }
    sm[tid] = m; ss[tid] = s;
    __syncthreads();
    for (int st = 128; st > 0; st >>= 1) {
        if (tid < st) {
            float m2 = sm[tid + st], s2 = ss[tid + st];
            float nm = fmaxf(sm[tid], m2);
            ss[tid] = ss[tid] * __expf(sm[tid] - nm) + s2 * __expf(m2 - nm);
            sm[tid] = nm;
        }
        __syncthreads();
    }
    if (tid == 0) {
        g_rm[bi]  = sm[0];
        g_rdi[bi] = 1.0f / (ss[0] + EPSV);
    }
}

// ============================================================
// K3a: column partial stats over 256-row chunks.
// grid (8 jtiles, 8 ichunks, B), block 256; one column per thread.
// ============================================================
__global__ __launch_bounds__(256) void k_colpart(
    const float* __restrict__ S, const float* __restrict__ M)
{
    const int b = blockIdx.z, jt = blockIdx.x, ic = blockIdx.y;
    const int tid = threadIdx.x;
    const int j = jt * 256 + tid;
    const size_t base = ((size_t)b * L + (size_t)ic * 256) * L + j;
    float m = -3.0e38f, s = 0.f;
    for (int r = 0; r < 256; r += 8) {
        float x[8], mk[8];
#pragma unroll
        for (int u = 0; u < 8; u++) {
            x[u]  = S[base + (size_t)(r + u) * L];
            mk[u] = M[base + (size_t)(r + u) * L];
        }
#pragma unroll
        for (int u = 0; u < 8; u++) {
            float nm = fmaxf(m, x[u]);
            s = s * __expf(m - nm) + mk[u] * __expf(x[u] - nm);
            m = nm;
        }
    }
    const size_t idx = (size_t)ic * (BB * L) + (size_t)b * L + j;
    g_cpm[idx] = m;
    g_cps[idx] = s;
}

// K3b: merge 8 partials per column.  grid 128, block 256.
__global__ __launch_bounds__(256) void k_colmerge()
{
    const int c = blockIdx.x * 256 + threadIdx.x;   // 0 .. B*L-1
    float m = -3.0e38f, s = 0.f;
#pragma unroll
    for (int ic = 0; ic < 8; ic++) {
        float m2 = g_cpm[(size_t)ic * (BB * L) + c];
        float s2 = g_cps[(size_t)ic * (BB * L) + c];
        float nm = fmaxf(m, m2);
        s = s * __expf(m - nm) + s2 * __expf(m2 - nm);
        m = nm;
    }
    g_cm[c]  = m;
    g_cdi[c] = 1.0f / (s + EPSV);
}

// ============================================================
// K4: fused gate + output GEMM.
//  gated = mask * exp(2S - rm_i - cm_j) * rdi_i * cdi_j   (in place over S)
//  out[b,i,:] += gated @ v   accumulated per 128-row tile, j in chunks of 32.
// grid (L/128, B), block 256, 8x8 output micro-tile per thread.
// ============================================================
__global__ __launch_bounds__(256) void k_gate_out(
    float* __restrict__ Sg, const float* __restrict__ M,
    const float* __restrict__ v, float* __restrict__ out)
{
    __shared__ float Gs[32][132];   // gated chunk, transposed [j'][i']
    __shared__ float Vs[32][128];   // v chunk [j'][d]
    __shared__ float rm_s[128], rdi_s[128];
    __shared__ float cm_s[32], cdi_s[32];

    const int b  = blockIdx.y;
    const int i0 = blockIdx.x * 128;
    const int tid = threadIdx.x;
    const int tx = tid & 15, ty = tid >> 4;

    if (tid < 128) {
        rm_s[tid]  = g_rm [(size_t)b * L + i0 + tid];
        rdi_s[tid] = g_rdi[(size_t)b * L + i0 + tid];
    }

    float acc[8][8];
#pragma unroll
    for (int m = 0; m < 8; m++)
#pragma unroll
        for (int n = 0; n < 8; n++) acc[m][n] = 0.f;

    float*       Sb = Sg + ((size_t)b * L + i0) * L;
    const float* Mb = M  + ((size_t)b * L + i0) * L;
    const float* vb = v  + (size_t)b * L * DV;

    for (int jt = 0; jt < L / 32; jt++) {
        const int j0 = jt * 32;
        if (tid < 32) {
            cm_s[tid]  = g_cm [(size_t)b * L + j0 + tid];
            cdi_s[tid] = g_cdi[(size_t)b * L + j0 + tid];
        }
        // load v chunk [32 x 128]
#pragma unroll
        for (int r = 0; r < 4; r++) {
            int f  = r * 256 + tid;
            int vr = f >> 5;
            int vc = f & 31;
            *reinterpret_cast<float4*>(&Vs[vr][vc * 4]) =
                *reinterpret_cast<const float4*>(vb + (size_t)(j0 + vr) * DV + vc * 4);
        }
        __syncthreads();   // cm/cdi + Vs ready; (first iter: rm_s too)

        // gating pass: 128 rows x 32 cols
#pragma unroll
        for (int p = 0; p < 4; p++) {
            int f   = p * 256 + tid;
            int row = f >> 3;
            int c4  = f & 7;
            size_t off = (size_t)row * L + j0 + c4 * 4;
            float4 s4 = *reinterpret_cast<const float4*>(Sb + off);
            float4 m4 = *reinterpret_cast<const float4*>(Mb + off);
            float rm = rm_s[row], rdi = rdi_s[row];
            float g0 = m4.x * __expf(2.f * s4.x - rm - cm_s[c4 * 4 + 0]) * rdi * cdi_s[c4 * 4 + 0];
            float g1 = m4.y * __expf(2.f * s4.y - rm - cm_s[c4 * 4 + 1]) * rdi * cdi_s[c4 * 4 + 1];
            float g2 = m4.z * __expf(2.f * s4.z - rm - cm_s[c4 * 4 + 2]) * rdi * cdi_s[c4 * 4 + 2];
            float g3 = m4.w * __expf(2.f * s4.w - rm - cm_s[c4 * 4 + 3]) * rdi * cdi_s[c4 * 4 + 3];
            *reinterpret_cast<float4*>(Sb + off) = make_float4(g0, g1, g2, g3);
            Gs[c4 * 4 + 0][row] = g0; Gs[c4 * 4 + 1][row] = g1;
            Gs[c4 * 4 + 2][row] = g2; Gs[c4 * 4 + 3][row] = g3;
        }
        __syncthreads();

        // GEMM step: acc += Gs^T(128x32) @ Vs(32x128)
#pragma unroll
        for (int kk = 0; kk < 32; kk++) {
            float a[8], bv[8];
            *reinterpret_cast<float4*>(a)      = *reinterpret_cast<const float4*>(&Gs[kk][ty * 8]);
            *reinterpret_cast<float4*>(a + 4)  = *reinterpret_cast<const float4*>(&Gs[kk][ty * 8 + 4]);
            *reinterpret_cast<float4*>(bv)     = *reinterpret_cast<const float4*>(&Vs[kk][tx * 8]);
            *reinterpret_cast<float4*>(bv + 4) = *reinterpret_cast<const float4*>(&Vs[kk][tx * 8 + 4]);
#pragma unroll
            for (int m = 0; m < 8; m++)
#pragma unroll
                for (int n = 0; n < 8; n++) acc[m][n] += a[m] * bv[n];
        }
        __syncthreads();
    }

    float* ob = out + ((size_t)b * L + i0) * DV;
#pragma unroll
    for (int m = 0; m < 8; m++) {
        float* row = ob + (size_t)(ty * 8 + m) * DV + tx * 8;
        *reinterpret_cast<float4*>(row)     = make_float4(acc[m][0], acc[m][1], acc[m][2], acc[m][3]);
        *reinterpret_cast<float4*>(row + 4) = make_float4(acc[m][4], acc[m][5], acc[m][6], acc[m][7]);
    }
}

// ============================================================
extern "C" void kernel_launch(void* const* d_in, const int* in_sizes, int n_in,
                              void* d_out, int out_size)
{
    const float* q    = (const float*)d_in[0];
    const float* kmat = (const float*)d_in[1];
    const float* v    = (const float*)d_in[2];
    const float* mask = (const float*)d_in[3];

    float* out   = (float*)d_out;                       // [B, L, DV]
    float* gated = out + (size_t)BB * L * DV;           // [B, L, L]  (S scratch, then gated)

    // 1) S = q k^T  (into gated region)
    k_gemm_qk<<<dim3(L / 128, L / 128, BB), 256>>>(q, kmat, gated);
    // 2) row stats
    k_rowstats<<<BB * L, 256>>>(gated, mask);
    // 3) col stats (partials + merge)
    k_colpart<<<dim3(8, 8, BB), 256>>>(gated, mask);
    k_colmerge<<<(BB * L) / 256, 256>>>();
    // 4) gate (in place) + output GEMM
    k_gate_out<<<dim3(L / 128, BB), 256>>>(gated, mask, v, out);
}

// round 3
// speedup vs baseline: 1.6597x; 1.6597x over previous
#include <cuda_runtime.h>
#include <cuda_bf16.h>
#include <math.h>
#include <stdint.h>

#define BB 16
#define L  2048
#define D  128
#define DV 128
#define EPSV 1e-12f
#define BL (BB * L)

#define PITCH  136                // bf16 elements per padded smem row
#define PITCHB 272                // bytes per row
#define TILEB  (128 * PITCHB)     // 34816 bytes per 128x128 bf16 tile
#define SMEM_TOT (4 * TILEB)      // 139264

// ---- device scratch (no allocation allowed) ----
__device__ float g_prm[32 * BL];            // row-max partials
__device__ float g_rm[BL];                  // row max
__device__ float g_R [BL];                  // exp(row max)
__device__ float g_F [BL];                  // exp(rm)/(rowsum+eps)
__device__ float g_cps[8 * BL];             // col-sum partials of T = sum_i E*R
__device__ float g_cdi[BL];                 // 1/(T+eps)
__device__ __nv_bfloat16 g_vTh[BB * D * L]; // v^T hi  [b][d][j]
__device__ __nv_bfloat16 g_vTl[BB * D * L]; // v^T lo
__device__ float g_opart[4 * (size_t)BB * L * DV];

// ================= helpers =================
__device__ __forceinline__ uint32_t smem_u32(const void* p) {
    uint32_t a;
    asm("{ .reg .u64 t; cvta.to.shared.u64 t, %1; cvt.u32.u64 %0, t; }" : "=r"(a) : "l"(p));
    return a;
}
__device__ __forceinline__ void ldm_x4(uint32_t* r, uint32_t addr) {
    asm volatile("ldmatrix.sync.aligned.m8n8.x4.shared.b16 {%0,%1,%2,%3}, [%4];"
        : "=r"(r[0]), "=r"(r[1]), "=r"(r[2]), "=r"(r[3]) : "r"(addr));
}
__device__ __forceinline__ void mma_bf16(float* c, const uint32_t* a, const uint32_t* b) {
    asm volatile("mma.sync.aligned.m16n8k16.row.col.f32.bf16.bf16.f32 "
        "{%0,%1,%2,%3}, {%4,%5,%6,%7}, {%8,%9}, {%0,%1,%2,%3};"
        : "+f"(c[0]), "+f"(c[1]), "+f"(c[2]), "+f"(c[3])
        : "r"(a[0]), "r"(a[1]), "r"(a[2]), "r"(a[3]), "r"(b[0]), "r"(b[1]));
}
__device__ __forceinline__ void split4(float4 a, uint2& h, uint2& l) {
    __nv_bfloat16 h0 = __float2bfloat16(a.x), h1 = __float2bfloat16(a.y);
    __nv_bfloat16 h2 = __float2bfloat16(a.z), h3 = __float2bfloat16(a.w);
    float l0 = a.x - __bfloat162float(h0), l1 = a.y - __bfloat162float(h1);
    float l2 = a.z - __bfloat162float(h2), l3 = a.w - __bfloat162float(h3);
    __nv_bfloat162 ph0{h0, h1}, ph1{h2, h3};
    __nv_bfloat162 pl0{__float2bfloat16(l0), __float2bfloat16(l1)};
    __nv_bfloat162 pl1{__float2bfloat16(l2), __float2bfloat16(l3)};
    h = make_uint2(*reinterpret_cast<uint32_t*>(&ph0), *reinterpret_cast<uint32_t*>(&ph1));
    l = make_uint2(*reinterpret_cast<uint32_t*>(&pl0), *reinterpret_cast<uint32_t*>(&pl1));
}

// ============================================================
// K0: v^T split:  g_vTh/g_vTl[b][d][j] = bf16 hi/lo of v[b][j][d]
// grid (L/32, D/32, B), block (32,8)
// ============================================================
__global__ void k_split_v(const float* __restrict__ v)
{
    __shared__ float tile[32][33];
    const int b = blockIdx.z, j0 = blockIdx.x * 32, d0 = blockIdx.y * 32;
    const int tx = threadIdx.x, ty = threadIdx.y;
#pragma unroll
    for (int i = 0; i < 4; i++)
        tile[ty + i * 8][tx] = v[((size_t)b * L + j0 + ty + i * 8) * DV + d0 + tx];
    __syncthreads();
#pragma unroll
    for (int i = 0; i < 4; i++) {
        float x = tile[tx][ty + i * 8];
        __nv_bfloat16 h = __float2bfloat16(x);
        __nv_bfloat16 lo = __float2bfloat16(x - __bfloat162float(h));
        size_t idx = ((size_t)b * D + d0 + ty + i * 8) * L + j0 + tx;
        g_vTh[idx] = h;
        g_vTl[idx] = lo;
    }
}

// ============================================================
// K1: S = q k^T via mma.sync bf16 hi/lo 3-pass + row-max partials.
// grid (16 jt, 16 it, B), block 256 (8 warps, each 32x64).
// ============================================================
__global__ __launch_bounds__(256) void k_gemm_qk_mma(
    const float* __restrict__ q, const float* __restrict__ kmat,
    float* __restrict__ S)
{
    extern __shared__ __align__(16) char smem[];
    const int tid = threadIdx.x;
    const int w = tid >> 5, lane = tid & 31;
    const int b = blockIdx.z;
    const int i0 = blockIdx.y * 128;
    const int j0 = blockIdx.x * 128;

    const uint32_t bqh = smem_u32(smem);
    const uint32_t bql = bqh + TILEB;
    const uint32_t bkh = bqh + 2 * TILEB;
    const uint32_t bkl = bqh + 3 * TILEB;

    // load q/k tiles, split hi/lo into padded smem
    const float* qb = q    + ((size_t)b * L + i0) * D;
    const float* kb = kmat + ((size_t)b * L + j0) * D;
#pragma unroll
    for (int it = 0; it < 16; it++) {
        int f = it * 256 + tid;
        int row = f >> 5, c4 = f & 31;
        uint32_t so = (uint32_t)row * PITCHB + (uint32_t)c4 * 8;
        uint2 h, l;
        split4(*reinterpret_cast<const float4*>(qb + (size_t)row * D + c4 * 4), h, l);
        *reinterpret_cast<uint2*>(smem + so)          = h;
        *reinterpret_cast<uint2*>(smem + TILEB + so)  = l;
        split4(*reinterpret_cast<const float4*>(kb + (size_t)row * D + c4 * 4), h, l);
        *reinterpret_cast<uint2*>(smem + 2 * TILEB + so) = h;
        *reinterpret_cast<uint2*>(smem + 3 * TILEB + so) = l;
    }
    __syncthreads();

    const int wr = w & 3, wc = w >> 2;
    float acc[2][8][4];
#pragma unroll
    for (int mt = 0; mt < 2; mt++)
#pragma unroll
        for (int nt = 0; nt < 8; nt++)
#pragma unroll
            for (int u = 0; u < 4; u++) acc[mt][nt][u] = 0.f;

#pragma unroll
    for (int ks = 0; ks < 8; ks++) {
        const uint32_t kb0 = ks * 32;
        uint32_t Ah[2][4], Al[2][4], Bh[4][4], Bl[4][4];
        uint32_t arow = (uint32_t)(wr * 32 + (lane & 15)) * PITCHB + kb0 + ((lane >> 4) << 4);
#pragma unroll
        for (int mt = 0; mt < 2; mt++) {
            uint32_t ad = arow + mt * 16 * PITCHB;
            ldm_x4(Ah[mt], bqh + ad);
            ldm_x4(Al[mt], bql + ad);
        }
        uint32_t brow = (uint32_t)(wc * 64 + (lane & 7) + ((lane >> 4) << 3)) * PITCHB
                      + kb0 + (((lane >> 3) & 1) << 4);
#pragma unroll
        for (int ntp = 0; ntp < 4; ntp++) {
            uint32_t bd = brow + ntp * 16 * PITCHB;
            ldm_x4(Bh[ntp], bkh + bd);
            ldm_x4(Bl[ntp], bkl + bd);
        }
#pragma unroll
        for (int mt = 0; mt < 2; mt++)
#pragma unroll
            for (int ntp = 0; ntp < 4; ntp++) {
                mma_bf16(acc[mt][2 * ntp],     Ah[mt], &Bh[ntp][0]);
                mma_bf16(acc[mt][2 * ntp + 1], Ah[mt], &Bh[ntp][2]);
                mma_bf16(acc[mt][2 * ntp],     Al[mt], &Bh[ntp][0]);
                mma_bf16(acc[mt][2 * ntp + 1], Al[mt], &Bh[ntp][2]);
                mma_bf16(acc[mt][2 * ntp],     Ah[mt], &Bl[ntp][0]);
                mma_bf16(acc[mt][2 * ntp + 1], Ah[mt], &Bl[ntp][2]);
            }
    }
    __syncthreads();   // done with bf16 tiles; reuse smem as fp32 stage

    float* St = reinterpret_cast<float*>(smem);
    const int tr = lane >> 2, tc = lane & 3;
#pragma unroll
    for (int mt = 0; mt < 2; mt++)
#pragma unroll
        for (int nt = 0; nt < 8; nt++) {
            int r0 = wr * 32 + mt * 16 + tr;
            int c0 = wc * 64 + nt * 8 + tc * 2;
            St[r0 * 132 + c0]           = acc[mt][nt][0];
            St[r0 * 132 + c0 + 1]       = acc[mt][nt][1];
            St[(r0 + 8) * 132 + c0]     = acc[mt][nt][2];
            St[(r0 + 8) * 132 + c0 + 1] = acc[mt][nt][3];
        }
    __syncthreads();

    // row-max partials (two 64-col halves per row)
    {
        int row = tid >> 1, half = tid & 1;
        const float* rp = &St[row * 132 + half * 64];
        float m = rp[0];
#pragma unroll
        for (int c = 1; c < 64; c++) m = fmaxf(m, rp[c]);
        g_prm[(size_t)(blockIdx.x * 2 + half) * BL + (size_t)b * L + i0 + row] = m;
    }
    // coalesced S write
    float* Sb = S + ((size_t)b * L + i0) * L + j0;
#pragma unroll
    for (int it = 0; it < 16; it++) {
        int f = it * 256 + tid;
        int r = f >> 5, c4 = f & 31;
        *reinterpret_cast<float4*>(Sb + (size_t)r * L + c4 * 4) =
            *reinterpret_cast<const float4*>(&St[r * 132 + c4 * 4]);
    }
}

// ============================================================
// K2: merge row-max partials -> rm, R=exp(rm)
// ============================================================
__global__ __launch_bounds__(256) void k_rowmax_merge()
{
    const int idx = blockIdx.x * 256 + threadIdx.x;
    float m = -3.0e38f;
#pragma unroll
    for (int p = 0; p < 32; p++) m = fmaxf(m, g_prm[(size_t)p * BL + idx]);
    g_rm[idx] = m;
    g_R[idx]  = expf(m);
}

// ============================================================
// K3: E = mask*exp(S - rm_i) in place; rowsum -> F = R/(sum+eps)
// ============================================================
__global__ __launch_bounds__(256) void k_rowsum_E(
    float* __restrict__ S, const float* __restrict__ M)
{
    __shared__ float ss[256];
    const size_t bi = blockIdx.x;
    float* Sr = S + bi * L;
    const float* Mr = M + bi * L;
    const int tid = threadIdx.x;
    const float rm = g_rm[bi];
    float s = 0.f;
#pragma unroll
    for (int it = 0; it < 2; it++) {
        int c = (it * 256 + tid) * 4;
        float4 x  = *reinterpret_cast<const float4*>(Sr + c);
        float4 mk = *reinterpret_cast<const float4*>(Mr + c);
        float e0 = mk.x * __expf(x.x - rm);
        float e1 = mk.y * __expf(x.y - rm);
        float e2 = mk.z * __expf(x.z - rm);
        float e3 = mk.w * __expf(x.w - rm);
        *reinterpret_cast<float4*>(Sr + c) = make_float4(e0, e1, e2, e3);
        s += (e0 + e1) + (e2 + e3);
    }
    ss[tid] = s;
    __syncthreads();
    for (int st = 128; st > 0; st >>= 1) {
        if (tid < st) ss[tid] += ss[tid + st];
        __syncthreads();
    }
    if (tid == 0) g_F[bi] = g_R[bi] / (ss[0] + EPSV);
}

// ============================================================
// K4a/b: column sums of T = sum_i E*R_i
// ============================================================
__global__ __launch_bounds__(256) void k_colsum_part(const float* __restrict__ E)
{
    const int b = blockIdx.z, jt = blockIdx.x, ic = blockIdx.y;
    const int tid = threadIdx.x;
    const int j = jt * 256 + tid;
    const size_t rbase = (size_t)b * L + (size_t)ic * 256;
    const size_t base = rbase * L + j;
    float s = 0.f;
    for (int r = 0; r < 256; r += 8) {
        float acc = 0.f;
#pragma unroll
        for (int u = 0; u < 8; u++)
            acc += E[base + (size_t)(r + u) * L] * g_R[rbase + r + u];
        s += acc;
    }
    g_cps[(size_t)ic * BL + (size_t)b * L + j] = s;
}
__global__ __launch_bounds__(256) void k_colsum_merge()
{
    const int c = blockIdx.x * 256 + threadIdx.x;
    float s = 0.f;
#pragma unroll
    for (int ic = 0; ic < 8; ic++) s += g_cps[(size_t)ic * BL + c];
    g_cdi[c] = 1.0f / (s + EPSV);
}

// ============================================================
// K5: gated = E^2 * F_i * cdi_j (in place) + out-partial = gated @ v (mma)
// grid (16 it, 4 ksplit, B), block 256.
// ============================================================
__global__ __launch_bounds__(256) void k_gate_out_mma(float* __restrict__ Eg)
{
    extern __shared__ __align__(16) char smem[];
    __shared__ float F_s[128];
    __shared__ float cd_s[128];

    const int tid = threadIdx.x;
    const int w = tid >> 5, lane = tid & 31;
    const int b = blockIdx.z;
    const int i0 = blockIdx.x * 128;
    const int ks = blockIdx.y;

    const uint32_t bgh = smem_u32(smem);
    const uint32_t bgl = bgh + TILEB;
    const uint32_t bvh = bgh + 2 * TILEB;
    const uint32_t bvl = bgh + 3 * TILEB;

    if (tid < 128) F_s[tid] = g_F[(size_t)b * L + i0 + tid];

    const int wr = w & 3, wc = w >> 2;
    float acc[2][8][4];
#pragma unroll
    for (int mt = 0; mt < 2; mt++)
#pragma unroll
        for (int nt = 0; nt < 8; nt++)
#pragma unroll
            for (int u = 0; u < 4; u++) acc[mt][nt][u] = 0.f;

    float* Eb = Eg + ((size_t)b * L + i0) * L;

    for (int jc = 0; jc < 4; jc++) {
        const int j0 = (ks * 4 + jc) * 128;
        if (tid < 32)
            *reinterpret_cast<float4*>(&cd_s[tid * 4]) =
                *reinterpret_cast<const float4*>(&g_cdi[(size_t)b * L + j0 + tid * 4]);
        __syncthreads();

        // gate + write gated + split into smem
#pragma unroll
        for (int it = 0; it < 16; it++) {
            int f = it * 256 + tid;
            int row = f >> 5, c4 = f & 31;
            size_t off = (size_t)row * L + j0 + c4 * 4;
            float4 e = *reinterpret_cast<const float4*>(Eb + off);
            float4 cd = *reinterpret_cast<const float4*>(&cd_s[c4 * 4]);
            float Fi = F_s[row];
            float4 g;
            g.x = e.x * e.x * Fi * cd.x;
            g.y = e.y * e.y * Fi * cd.y;
            g.z = e.z * e.z * Fi * cd.z;
            g.w = e.w * e.w * Fi * cd.w;
            *reinterpret_cast<float4*>(Eb + off) = g;
            uint2 h, l;
            split4(g, h, l);
            uint32_t so = (uint32_t)row * PITCHB + (uint32_t)c4 * 8;
            *reinterpret_cast<uint2*>(smem + so)         = h;
            *reinterpret_cast<uint2*>(smem + TILEB + so) = l;
        }
        // load v^T tiles (bf16 hi/lo), [d][j] with j contiguous
        const __nv_bfloat16* vh = g_vTh + (size_t)b * D * L + j0;
        const __nv_bfloat16* vl = g_vTl + (size_t)b * D * L + j0;
#pragma unroll
        for (int it = 0; it < 16; it++) {
            int f = it * 256 + tid;
            int row = f >> 5, c4 = f & 31;
            uint32_t so = (uint32_t)row * PITCHB + (uint32_t)c4 * 8;
            *reinterpret_cast<uint2*>(smem + 2 * TILEB + so) =
                *reinterpret_cast<const uint2*>(vh + (size_t)row * L + c4 * 4);
            *reinterpret_cast<uint2*>(smem + 3 * TILEB + so) =
                *reinterpret_cast<const uint2*>(vl + (size_t)row * L + c4 * 4);
        }
        __syncthreads();

#pragma unroll
        for (int kss = 0; kss < 8; kss++) {
            const uint32_t kb0 = kss * 32;
            uint32_t Ah[2][4], Al[2][4], Bh[4][4], Bl[4][4];
            uint32_t arow = (uint32_t)(wr * 32 + (lane & 15)) * PITCHB + kb0 + ((lane >> 4) << 4);
#pragma unroll
            for (int mt = 0; mt < 2; mt++) {
                uint32_t ad = arow + mt * 16 * PITCHB;
                ldm_x4(Ah[mt], bgh + ad);
                ldm_x4(Al[mt], bgl + ad);
            }
            uint32_t brow = (uint32_t)(wc * 64 + (lane & 7) + ((lane >> 4) << 3)) * PITCHB
                          + kb0 + (((lane >> 3) & 1) << 4);
#pragma unroll
            for (int ntp = 0; ntp < 4; ntp++) {
                uint32_t bd = brow + ntp * 16 * PITCHB;
                ldm_x4(Bh[ntp], bvh + bd);
                ldm_x4(Bl[ntp], bvl + bd);
            }
#pragma unroll
            for (int mt = 0; mt < 2; mt++)
#pragma unroll
                for (int ntp = 0; ntp < 4; ntp++) {
                    mma_bf16(acc[mt][2 * ntp],     Ah[mt], &Bh[ntp][0]);
                    mma_bf16(acc[mt][2 * ntp + 1], Ah[mt], &Bh[ntp][2]);
                    mma_bf16(acc[mt][2 * ntp],     Al[mt], &Bh[ntp][0]);
                    mma_bf16(acc[mt][2 * ntp + 1], Al[mt], &Bh[ntp][2]);
                    mma_bf16(acc[mt][2 * ntp],     Ah[mt], &Bl[ntp][0]);
                    mma_bf16(acc[mt][2 * ntp + 1], Ah[mt], &Bl[ntp][2]);
                }
        }
        __syncthreads();
    }

    // stage + write output partial
    float* St = reinterpret_cast<float*>(smem);
    const int tr = lane >> 2, tc = lane & 3;
#pragma unroll
    for (int mt = 0; mt < 2; mt++)
#pragma unroll
        for (int nt = 0; nt < 8; nt++) {
            int r0 = wr * 32 + mt * 16 + tr;
            int c0 = wc * 64 + nt * 8 + tc * 2;
            St[r0 * 132 + c0]           = acc[mt][nt][0];
            St[r0 * 132 + c0 + 1]       = acc[mt][nt][1];
            St[(r0 + 8) * 132 + c0]     = acc[mt][nt][2];
            St[(r0 + 8) * 132 + c0 + 1] = acc[mt][nt][3];
        }
    __syncthreads();
    float* op = g_opart + (((size_t)ks * BB + b) * L + i0) * DV;
#pragma unroll
    for (int it = 0; it < 16; it++) {
        int f = it * 256 + tid;
        int r = f >> 5, c4 = f & 31;
        *reinterpret_cast<float4*>(op + (size_t)r * DV + c4 * 4) =
            *reinterpret_cast<const float4*>(&St[r * 132 + c4 * 4]);
    }
}

// K6: reduce 4 output partials
__global__ __launch_bounds__(256) void k_out_reduce(float* __restrict__ out)
{
    const size_t i = ((size_t)blockIdx.x * 256 + threadIdx.x) * 4;
    const size_t n = (size_t)BB * L * DV;
    float4 a = *reinterpret_cast<const float4*>(&g_opart[i]);
    float4 bq = *reinterpret_cast<const float4*>(&g_opart[n + i]);
    float4 c = *reinterpret_cast<const float4*>(&g_opart[2 * n + i]);
    float4 d = *reinterpret_cast<const float4*>(&g_opart[3 * n + i]);
    float4 r;
    r.x = (a.x + bq.x) + (c.x + d.x);
    r.y = (a.y + bq.y) + (c.y + d.y);
    r.z = (a.z + bq.z) + (c.z + d.z);
    r.w = (a.w + bq.w) + (c.w + d.w);
    *reinterpret_cast<float4*>(out + i) = r;
}

// ============================================================
extern "C" void kernel_launch(void* const* d_in, const int* in_sizes, int n_in,
                              void* d_out, int out_size)
{
    const float* q    = (const float*)d_in[0];
    const float* kmat = (const float*)d_in[1];
    const float* v    = (const float*)d_in[2];
    const float* mask = (const float*)d_in[3];

    float* out   = (float*)d_out;
    float* gated = out + (size_t)BB * L * DV;   // S -> E -> gated, in place

    cudaFuncSetAttribute(k_gemm_qk_mma,  cudaFuncAttributeMaxDynamicSharedMemorySize, SMEM_TOT);
    cudaFuncSetAttribute(k_gate_out_mma, cudaFuncAttributeMaxDynamicSharedMemorySize, SMEM_TOT);

    k_split_v<<<dim3(L / 32, D / 32, BB), dim3(32, 8)>>>(v);
    k_gemm_qk_mma<<<dim3(16, 16, BB), 256, SMEM_TOT>>>(q, kmat, gated);
    k_rowmax_merge<<<BL / 256, 256>>>();
    k_rowsum_E<<<BL, 256>>>(gated, mask);
    k_colsum_part<<<dim3(8, 8, BB), 256>>>(gated);
    k_colsum_merge<<<BL / 256, 256>>>();
    k_gate_out_mma<<<dim3(16, 4, BB), 256, SMEM_TOT>>>(gated);
    k_out_reduce<<<(BB * L * DV) / 1024, 256>>>(out);
}

// round 4
// speedup vs baseline: 1.7660x; 1.0640x over previous
#include <cuda_runtime.h>
#include <cuda_bf16.h>
#include <math.h>
#include <stdint.h>

#define BB 16
#define L  2048
#define D  128
#define DV 128
#define EPSV 1e-12f
#define BL (BB * L)

#define PITCHB 272                 // bytes per smem tile row (128 bf16 + pad)
#define TILEB  (128 * PITCHB)      // 34816 B per 128x128 bf16 tile
#define SMEM6  (6 * TILEB)         // 208896 B

// ---- device scratch ----
__device__ float g_prm[32 * BL];
__device__ float g_rm[BL];
__device__ float g_R [BL];
__device__ float g_F [BL];
__device__ float g_cps[16 * BL];
__device__ float g_cdi[BL];
__device__ __nv_bfloat16 g_qh[BB * L * D], g_ql[BB * L * D];
__device__ __nv_bfloat16 g_kh[BB * L * D], g_kl[BB * L * D];
__device__ __nv_bfloat16 g_vTh[BB * D * L], g_vTl[BB * D * L]; // [b][d][j]
__device__ float g_opart[2 * (size_t)BB * L * DV];

// ================= helpers =================
__device__ __forceinline__ uint32_t smem_u32(const void* p) {
    uint32_t a;
    asm("{ .reg .u64 t; cvta.to.shared.u64 t, %1; cvt.u32.u64 %0, t; }" : "=r"(a) : "l"(p));
    return a;
}
__device__ __forceinline__ void ldm_x4(uint32_t* r, uint32_t addr) {
    asm volatile("ldmatrix.sync.aligned.m8n8.x4.shared.b16 {%0,%1,%2,%3}, [%4];"
        : "=r"(r[0]), "=r"(r[1]), "=r"(r[2]), "=r"(r[3]) : "r"(addr));
}
__device__ __forceinline__ void mma_bf16(float* c, const uint32_t* a, const uint32_t* b) {
    asm volatile("mma.sync.aligned.m16n8k16.row.col.f32.bf16.bf16.f32 "
        "{%0,%1,%2,%3}, {%4,%5,%6,%7}, {%8,%9}, {%0,%1,%2,%3};"
        : "+f"(c[0]), "+f"(c[1]), "+f"(c[2]), "+f"(c[3])
        : "r"(a[0]), "r"(a[1]), "r"(a[2]), "r"(a[3]), "r"(b[0]), "r"(b[1]));
}
#define CP16(dst, src) asm volatile("cp.async.cg.shared.global [%0], [%1], 16;" :: "r"(dst), "l"(src))
#define CP_COMMIT()    asm volatile("cp.async.commit_group;" ::: "memory")
#define CP_WAIT0()     asm volatile("cp.async.wait_group 0;" ::: "memory")
#define CP_WAIT1()     asm volatile("cp.async.wait_group 1;" ::: "memory")

__device__ __forceinline__ void split4(float4 a, uint2& h, uint2& l) {
    __nv_bfloat16 h0 = __float2bfloat16(a.x), h1 = __float2bfloat16(a.y);
    __nv_bfloat16 h2 = __float2bfloat16(a.z), h3 = __float2bfloat16(a.w);
    float l0 = a.x - __bfloat162float(h0), l1 = a.y - __bfloat162float(h1);
    float l2 = a.z - __bfloat162float(h2), l3 = a.w - __bfloat162float(h3);
    __nv_bfloat162 ph0{h0, h1}, ph1{h2, h3};
    __nv_bfloat162 pl0{__float2bfloat16(l0), __float2bfloat16(l1)};
    __nv_bfloat162 pl1{__float2bfloat16(l2), __float2bfloat16(l3)};
    h = make_uint2(*reinterpret_cast<uint32_t*>(&ph0), *reinterpret_cast<uint32_t*>(&ph1));
    l = make_uint2(*reinterpret_cast<uint32_t*>(&pl0), *reinterpret_cast<uint32_t*>(&pl1));
}

// ============================================================
// K0a: split q,k to bf16 hi/lo.  grid 4096, block 256, 4 elems/thread.
// ============================================================
__global__ __launch_bounds__(256) void k_split_qk(
    const float* __restrict__ q, const float* __restrict__ kmat)
{
    const size_t i = ((size_t)blockIdx.x * 256 + threadIdx.x) * 4;
    uint2 h, l;
    split4(*reinterpret_cast<const float4*>(q + i), h, l);
    *reinterpret_cast<uint2*>(&g_qh[i]) = h;
    *reinterpret_cast<uint2*>(&g_ql[i]) = l;
    split4(*reinterpret_cast<const float4*>(kmat + i), h, l);
    *reinterpret_cast<uint2*>(&g_kh[i]) = h;
    *reinterpret_cast<uint2*>(&g_kl[i]) = l;
}

// K0b: v^T split  [b][d][j]
__global__ void k_split_v(const float* __restrict__ v)
{
    __shared__ float tile[32][33];
    const int b = blockIdx.z, j0 = blockIdx.x * 32, d0 = blockIdx.y * 32;
    const int tx = threadIdx.x, ty = threadIdx.y;
#pragma unroll
    for (int i = 0; i < 4; i++)
        tile[ty + i * 8][tx] = v[((size_t)b * L + j0 + ty + i * 8) * DV + d0 + tx];
    __syncthreads();
#pragma unroll
    for (int i = 0; i < 4; i++) {
        float x = tile[tx][ty + i * 8];
        __nv_bfloat16 h = __float2bfloat16(x);
        __nv_bfloat16 lo = __float2bfloat16(x - __bfloat162float(h));
        size_t idx = ((size_t)b * D + d0 + ty + i * 8) * L + j0 + tx;
        g_vTh[idx] = h;
        g_vTl[idx] = lo;
    }
}

// ============================================================
// K1: S = q k^T, pipelined.  grid (4 jt4, 16 it, B), block 256.
// smem: q hi/lo + 2x (k hi/lo) double buffer = 6 tiles.
// ============================================================
__global__ __launch_bounds__(256) void k_gemm_qk_mma(float* __restrict__ S)
{
    extern __shared__ __align__(16) char smem[];
    const int tid = threadIdx.x;
    const int w = tid >> 5, lane = tid & 31;
    const int b = blockIdx.z;
    const int i0 = blockIdx.y * 128;
    const int jt4 = blockIdx.x;

    const uint32_t bq  = smem_u32(smem);
    const uint32_t bql = bq + TILEB;
    const uint32_t bk[2]  = {bq + 2 * TILEB, bq + 4 * TILEB};
    const uint32_t bkl[2] = {bq + 3 * TILEB, bq + 5 * TILEB};

    const __nv_bfloat16* qh = g_qh + ((size_t)b * L + i0) * D;
    const __nv_bfloat16* ql = g_ql + ((size_t)b * L + i0) * D;

    // issue q tiles + k tile 0
#pragma unroll
    for (int u = 0; u < 8; u++) {
        int f = u * 256 + tid;
        int row = f >> 4, c = f & 15;
        uint32_t so = (uint32_t)row * PITCHB + (uint32_t)c * 16;
        CP16(bq  + so, qh + (size_t)row * D + c * 8);
        CP16(bql + so, ql + (size_t)row * D + c * 8);
    }
    {
        const int j0 = jt4 * 512;
        const __nv_bfloat16* kh = g_kh + ((size_t)b * L + j0) * D;
        const __nv_bfloat16* kl = g_kl + ((size_t)b * L + j0) * D;
#pragma unroll
        for (int u = 0; u < 8; u++) {
            int f = u * 256 + tid;
            int row = f >> 4, c = f & 15;
            uint32_t so = (uint32_t)row * PITCHB + (uint32_t)c * 16;
            CP16(bk[0]  + so, kh + (size_t)row * D + c * 8);
            CP16(bkl[0] + so, kl + (size_t)row * D + c * 8);
        }
    }
    CP_COMMIT();

    const int wr = w & 3, wc = w >> 2;
    const int tr = lane >> 2, tc = lane & 3;

    for (int jl = 0; jl < 4; jl++) {
        const int jt = jt4 * 4 + jl;
        const int j0 = jt * 128;
        // prefetch next k
        if (jl < 3) {
            const int jn = j0 + 128;
            const __nv_bfloat16* kh = g_kh + ((size_t)b * L + jn) * D;
            const __nv_bfloat16* kl = g_kl + ((size_t)b * L + jn) * D;
            const uint32_t dh = bk[(jl + 1) & 1], dl = bkl[(jl + 1) & 1];
#pragma unroll
            for (int u = 0; u < 8; u++) {
                int f = u * 256 + tid;
                int row = f >> 4, c = f & 15;
                uint32_t so = (uint32_t)row * PITCHB + (uint32_t)c * 16;
                CP16(dh + so, kh + (size_t)row * D + c * 8);
                CP16(dl + so, kl + (size_t)row * D + c * 8);
            }
            CP_COMMIT();
            CP_WAIT1();
        } else {
            CP_WAIT0();
        }
        __syncthreads();

        float acc[2][8][4];
#pragma unroll
        for (int mt = 0; mt < 2; mt++)
#pragma unroll
            for (int nt = 0; nt < 8; nt++)
#pragma unroll
                for (int u = 0; u < 4; u++) acc[mt][nt][u] = 0.f;

        const uint32_t bkh = bk[jl & 1], bklo = bkl[jl & 1];
#pragma unroll
        for (int ks = 0; ks < 8; ks++) {
            const uint32_t kb0 = ks * 32;
            uint32_t Ah[2][4], Al[2][4], Bh[4][4], Bl[4][4];
            uint32_t arow = (uint32_t)(wr * 32 + (lane & 15)) * PITCHB + kb0 + ((lane >> 4) << 4);
#pragma unroll
            for (int mt = 0; mt < 2; mt++) {
                uint32_t ad = arow + mt * 16 * PITCHB;
                ldm_x4(Ah[mt], bq  + ad);
                ldm_x4(Al[mt], bql + ad);
            }
            uint32_t brow = (uint32_t)(wc * 64 + (lane & 7) + ((lane >> 4) << 3)) * PITCHB
                          + kb0 + (((lane >> 3) & 1) << 4);
#pragma unroll
            for (int ntp = 0; ntp < 4; ntp++) {
                uint32_t bd = brow + ntp * 16 * PITCHB;
                ldm_x4(Bh[ntp], bkh  + bd);
                ldm_x4(Bl[ntp], bklo + bd);
            }
#pragma unroll
            for (int mt = 0; mt < 2; mt++)
#pragma unroll
                for (int ntp = 0; ntp < 4; ntp++) {
                    mma_bf16(acc[mt][2 * ntp],     Ah[mt], &Bh[ntp][0]);
                    mma_bf16(acc[mt][2 * ntp + 1], Ah[mt], &Bh[ntp][2]);
                    mma_bf16(acc[mt][2 * ntp],     Al[mt], &Bh[ntp][0]);
                    mma_bf16(acc[mt][2 * ntp + 1], Al[mt], &Bh[ntp][2]);
                    mma_bf16(acc[mt][2 * ntp],     Ah[mt], &Bl[ntp][0]);
                    mma_bf16(acc[mt][2 * ntp + 1], Ah[mt], &Bl[ntp][2]);
                }
        }
        __syncthreads();   // all ldmatrix done before next prefetch overwrites

        // epilogue: row-max partials via quad shfl + direct float2 stores
        float mx[4] = {-3.0e38f, -3.0e38f, -3.0e38f, -3.0e38f};
#pragma unroll
        for (int mt = 0; mt < 2; mt++)
#pragma unroll
            for (int nt = 0; nt < 8; nt++) {
                mx[mt * 2]     = fmaxf(mx[mt * 2],     fmaxf(acc[mt][nt][0], acc[mt][nt][1]));
                mx[mt * 2 + 1] = fmaxf(mx[mt * 2 + 1], fmaxf(acc[mt][nt][2], acc[mt][nt][3]));
            }
#pragma unroll
        for (int u = 0; u < 4; u++) {
            mx[u] = fmaxf(mx[u], __shfl_xor_sync(0xFFFFFFFFu, mx[u], 1));
            mx[u] = fmaxf(mx[u], __shfl_xor_sync(0xFFFFFFFFu, mx[u], 2));
        }
        if (tc == 0) {
            float* pp = &g_prm[(size_t)(jt * 2 + wc) * BL + (size_t)b * L + i0 + wr * 32 + tr];
            pp[0] = mx[0]; pp[8] = mx[1]; pp[16] = mx[2]; pp[24] = mx[3];
        }
        float* Sb = S + ((size_t)b * L + i0) * L + j0;
#pragma unroll
        for (int mt = 0; mt < 2; mt++)
#pragma unroll
            for (int nt = 0; nt < 8; nt++) {
                int r = wr * 32 + mt * 16 + tr;
                int cc = wc * 64 + nt * 8 + tc * 2;
                *reinterpret_cast<float2*>(Sb + (size_t)r * L + cc) =
                    make_float2(acc[mt][nt][0], acc[mt][nt][1]);
                *reinterpret_cast<float2*>(Sb + (size_t)(r + 8) * L + cc) =
                    make_float2(acc[mt][nt][2], acc[mt][nt][3]);
            }
    }
}

// ============================================================
// K2: merge row-max partials -> rm, R = exp(rm)
// ============================================================
__global__ __launch_bounds__(256) void k_rowmax_merge()
{
    const int idx = blockIdx.x * 256 + threadIdx.x;
    float m = -3.0e38f;
#pragma unroll
    for (int p = 0; p < 32; p++) m = fmaxf(m, g_prm[(size_t)p * BL + idx]);
    g_rm[idx] = m;
    g_R[idx]  = expf(m);
}

// ============================================================
// K3: fused E-pass: E = mask*exp(S-rm) in place, row F, col partials of E*R.
// grid (16 slabs, B), block 256 (8 warps x 16 rows each).
// ============================================================
__global__ __launch_bounds__(256) void k_stats(
    float* __restrict__ S, const float* __restrict__ M)
{
    __shared__ float colacc[8][2048];
    const int b = blockIdx.y, slab = blockIdx.x;
    const int tid = threadIdx.x, w = tid >> 5, lane = tid & 31;

    for (int c = lane; c < 2048; c += 32) colacc[w][c] = 0.f;
    __syncwarp();

    for (int rr = 0; rr < 16; rr++) {
        const int row = slab * 128 + rr * 8 + w;
        const size_t bi = (size_t)b * L + row;
        const float rm = g_rm[bi], Ri = g_R[bi];
        float* Sr = S + bi * L;
        const float* Mr = M + bi * L;
        float sum = 0.f;
#pragma unroll
        for (int ch = 0; ch < 16; ch++) {
            int c = ch * 128 + lane * 4;
            float4 x  = *reinterpret_cast<const float4*>(Sr + c);
            float4 mk = *reinterpret_cast<const float4*>(Mr + c);
            float e0 = mk.x * __expf(x.x - rm);
            float e1 = mk.y * __expf(x.y - rm);
            float e2 = mk.z * __expf(x.z - rm);
            float e3 = mk.w * __expf(x.w - rm);
            *reinterpret_cast<float4*>(Sr + c) = make_float4(e0, e1, e2, e3);
            sum += (e0 + e1) + (e2 + e3);
            float4* ca = reinterpret_cast<float4*>(&colacc[w][c]);
            float4 cur = *ca;
            cur.x += e0 * Ri; cur.y += e1 * Ri; cur.z += e2 * Ri; cur.w += e3 * Ri;
            *ca = cur;
        }
#pragma unroll
        for (int o = 16; o > 0; o >>= 1) sum += __shfl_xor_sync(0xFFFFFFFFu, sum, o);
        if (lane == 0) g_F[bi] = Ri / (sum + EPSV);
    }
    __syncthreads();
#pragma unroll
    for (int u = 0; u < 8; u++) {
        int c = tid * 8 + u;
        float s = 0.f;
#pragma unroll
        for (int w2 = 0; w2 < 8; w2++) s += colacc[w2][c];
        g_cps[(size_t)slab * BL + (size_t)b * L + c] = s;
    }
}

// K4: merge 16 col partials -> cdi
__global__ __launch_bounds__(256) void k_colsum_merge()
{
    const int c = blockIdx.x * 256 + threadIdx.x;
    float s = 0.f;
#pragma unroll
    for (int p = 0; p < 16; p++) s += g_cps[(size_t)p * BL + c];
    g_cdi[c] = 1.0f / (s + EPSV);
}

// ============================================================
// K5: gate (in place) + out-partial = gated @ v, pipelined v.
// grid (16 it, 2 ks, B), block 256.  smem: g hi/lo + 2x (v hi/lo).
// ============================================================
__global__ __launch_bounds__(256) void k_gate_out_mma(float* __restrict__ Eg)
{
    extern __shared__ __align__(16) char smem[];
    __shared__ float F_s[128];
    __shared__ float cd_s[128];

    const int tid = threadIdx.x;
    const int w = tid >> 5, lane = tid & 31;
    const int b = blockIdx.z;
    const int i0 = blockIdx.x * 128;
    const int ks = blockIdx.y;

    const uint32_t bg  = smem_u32(smem);
    const uint32_t bgl = bg + TILEB;
    const uint32_t bv[2]  = {bg + 2 * TILEB, bg + 4 * TILEB};
    const uint32_t bvl[2] = {bg + 3 * TILEB, bg + 5 * TILEB};

    if (tid < 128) F_s[tid] = g_F[(size_t)b * L + i0 + tid];

    const int wr = w & 3, wc = w >> 2;
    const int tr = lane >> 2, tc = lane & 3;
    float acc[2][8][4];
#pragma unroll
    for (int mt = 0; mt < 2; mt++)
#pragma unroll
        for (int nt = 0; nt < 8; nt++)
#pragma unroll
            for (int u = 0; u < 4; u++) acc[mt][nt][u] = 0.f;

    float* Eb = Eg + ((size_t)b * L + i0) * L;
    const __nv_bfloat16* vhB = g_vTh + (size_t)b * D * L;
    const __nv_bfloat16* vlB = g_vTl + (size_t)b * D * L;

    // prefetch v(jc=0)
    {
        const int j0 = ks * 1024;
#pragma unroll
        for (int u = 0; u < 8; u++) {
            int f = u * 256 + tid;
            int row = f >> 4, c = f & 15;
            uint32_t so = (uint32_t)row * PITCHB + (uint32_t)c * 16;
            CP16(bv[0]  + so, vhB + (size_t)row * L + j0 + c * 8);
            CP16(bvl[0] + so, vlB + (size_t)row * L + j0 + c * 8);
        }
        CP_COMMIT();
    }

    for (int jc = 0; jc < 8; jc++) {
        const int j0 = (ks * 8 + jc) * 128;
        if (tid < 32)
            *reinterpret_cast<float4*>(&cd_s[tid * 4]) =
                *reinterpret_cast<const float4*>(&g_cdi[(size_t)b * L + j0 + tid * 4]);
        if (jc < 7) {   // prefetch next v
            const int jn = j0 + 128;
            const uint32_t dh = bv[(jc + 1) & 1], dl = bvl[(jc + 1) & 1];
#pragma unroll
            for (int u = 0; u < 8; u++) {
                int f = u * 256 + tid;
                int row = f >> 4, c = f & 15;
                uint32_t so = (uint32_t)row * PITCHB + (uint32_t)c * 16;
                CP16(dh + so, vhB + (size_t)row * L + jn + c * 8);
                CP16(dl + so, vlB + (size_t)row * L + jn + c * 8);
            }
            CP_COMMIT();
        }
        __syncthreads();   // cd_s/F_s visible; prev mma done -> g smem reusable

        // gate: read E, write gated, split -> smem
#pragma unroll
        for (int it = 0; it < 16; it++) {
            int f = it * 256 + tid;
            int row = f >> 5, c4 = f & 31;
            size_t off = (size_t)row * L + j0 + c4 * 4;
            float4 e = *reinterpret_cast<const float4*>(Eb + off);
            float4 cd = *reinterpret_cast<const float4*>(&cd_s[c4 * 4]);
            float Fi = F_s[row];
            float4 g;
            g.x = e.x * e.x * Fi * cd.x;
            g.y = e.y * e.y * Fi * cd.y;
            g.z = e.z * e.z * Fi * cd.z;
            g.w = e.w * e.w * Fi * cd.w;
            *reinterpret_cast<float4*>(Eb + off) = g;
            uint2 h, l;
            split4(g, h, l);
            uint32_t so = (uint32_t)row * PITCHB + (uint32_t)c4 * 8;
            *reinterpret_cast<uint2*>(smem + so)         = h;
            *reinterpret_cast<uint2*>(smem + TILEB + so) = l;
        }
        if (jc < 7) CP_WAIT1(); else CP_WAIT0();
        __syncthreads();

        const uint32_t bvh = bv[jc & 1], bvlo = bvl[jc & 1];
#pragma unroll
        for (int kss = 0; kss < 8; kss++) {
            const uint32_t kb0 = kss * 32;
            uint32_t Ah[2][4], Al[2][4], Bh[4][4], Bl[4][4];
            uint32_t arow = (uint32_t)(wr * 32 + (lane & 15)) * PITCHB + kb0 + ((lane >> 4) << 4);
#pragma unroll
            for (int mt = 0; mt < 2; mt++) {
                uint32_t ad = arow + mt * 16 * PITCHB;
                ldm_x4(Ah[mt], bg  + ad);
                ldm_x4(Al[mt], bgl + ad);
            }
            uint32_t brow = (uint32_t)(wc * 64 + (lane & 7) + ((lane >> 4) << 3)) * PITCHB
                          + kb0 + (((lane >> 3) & 1) << 4);
#pragma unroll
            for (int ntp = 0; ntp < 4; ntp++) {
                uint32_t bd = brow + ntp * 16 * PITCHB;
                ldm_x4(Bh[ntp], bvh  + bd);
                ldm_x4(Bl[ntp], bvlo + bd);
            }
#pragma unroll
            for (int mt = 0; mt < 2; mt++)
#pragma unroll
                for (int ntp = 0; ntp < 4; ntp++) {
                    mma_bf16(acc[mt][2 * ntp],     Ah[mt], &Bh[ntp][0]);
                    mma_bf16(acc[mt][2 * ntp + 1], Ah[mt], &Bh[ntp][2]);
                    mma_bf16(acc[mt][2 * ntp],     Al[mt], &Bh[ntp][0]);
                    mma_bf16(acc[mt][2 * ntp + 1], Al[mt], &Bh[ntp][2]);
                    mma_bf16(acc[mt][2 * ntp],     Ah[mt], &Bl[ntp][0]);
                    mma_bf16(acc[mt][2 * ntp + 1], Ah[mt], &Bl[ntp][2]);
                }
        }
        __syncthreads();   // ldmatrix done before next gate/prefetch overwrites
    }

    // out partial: direct float2 stores
    float* op = g_opart + (((size_t)ks * BB + b) * L + i0) * DV;
#pragma unroll
    for (int mt = 0; mt < 2; mt++)
#pragma unroll
        for (int nt = 0; nt < 8; nt++) {
            int r = wr * 32 + mt * 16 + tr;
            int cc = wc * 64 + nt * 8 + tc * 2;
            *reinterpret_cast<float2*>(op + (size_t)r * DV + cc) =
                make_float2(acc[mt][nt][0], acc[mt][nt][1]);
            *reinterpret_cast<float2*>(op + (size_t)(r + 8) * DV + cc) =
                make_float2(acc[mt][nt][2], acc[mt][nt][3]);
        }
}

// K6: reduce 2 output partials
__global__ __launch_bounds__(256) void k_out_reduce(float* __restrict__ out)
{
    const size_t i = ((size_t)blockIdx.x * 256 + threadIdx.x) * 4;
    const size_t n = (size_t)BB * L * DV;
    float4 a = *reinterpret_cast<const float4*>(&g_opart[i]);
    float4 bq = *reinterpret_cast<const float4*>(&g_opart[n + i]);
    float4 r;
    r.x = a.x + bq.x; r.y = a.y + bq.y; r.z = a.z + bq.z; r.w = a.w + bq.w;
    *reinterpret_cast<float4*>(out + i) = r;
}

// ============================================================
extern "C" void kernel_launch(void* const* d_in, const int* in_sizes, int n_in,
                              void* d_out, int out_size)
{
    const float* q    = (const float*)d_in[0];
    const float* kmat = (const float*)d_in[1];
    const float* v    = (const float*)d_in[2];
    const float* mask = (const float*)d_in[3];

    float* out   = (float*)d_out;
    float* gated = out + (size_t)BB * L * DV;   // S -> E -> gated in place

    cudaFuncSetAttribute(k_gemm_qk_mma,  cudaFuncAttributeMaxDynamicSharedMemorySize, SMEM6);
    cudaFuncSetAttribute(k_gate_out_mma, cudaFuncAttributeMaxDynamicSharedMemorySize, SMEM6);

    k_split_qk<<<(BB * L * D) / 1024, 256>>>(q, kmat);
    k_split_v<<<dim3(L / 32, D / 32, BB), dim3(32, 8)>>>(v);
    k_gemm_qk_mma<<<dim3(4, 16, BB), 256, SMEM6>>>(gated);
    k_rowmax_merge<<<BL / 256, 256>>>();
    k_stats<<<dim3(16, BB), 256>>>(gated, mask);
    k_colsum_merge<<<BL / 256, 256>>>();
    k_gate_out_mma<<<dim3(16, 2, BB), 256, SMEM6>>>(gated);
    k_out_reduce<<<(BB * L * DV) / 1024, 256>>>(out);
}

// round 5
// speedup vs baseline: 1.9216x; 1.0881x over previous
#include <cuda_runtime.h>
#include <cuda_bf16.h>
#include <math.h>
#include <stdint.h>

#define BB 16
#define L  2048
#define D  128
#define DV 128
#define EPSV 1e-12f
#define BL (BB * L)

#define PITCHB 272                 // bytes per smem tile row (128 bf16 + pad)
#define TILEB  (128 * PITCHB)      // 34816 B per 128x128 bf16 tile
#define SMEM6  (6 * TILEB)         // 208896 B

// ---- device scratch ----
__device__ float g_rps[8 * BL];    // row-sum partials
__device__ float g_cps[16 * BL];   // col-sum partials
__device__ float g_rdi[BL];        // 1/(rowsum+eps)
__device__ float g_cdi[BL];        // 1/(colsum+eps)
__device__ __nv_bfloat16 g_qh[BB * L * D], g_ql[BB * L * D];
__device__ __nv_bfloat16 g_kh[BB * L * D], g_kl[BB * L * D];
__device__ __nv_bfloat16 g_vTh[BB * D * L], g_vTl[BB * D * L]; // [b][d][j]
__device__ float g_opart[2 * (size_t)BB * L * DV];

// ================= helpers =================
__device__ __forceinline__ uint32_t smem_u32(const void* p) {
    uint32_t a;
    asm("{ .reg .u64 t; cvta.to.shared.u64 t, %1; cvt.u32.u64 %0, t; }" : "=r"(a) : "l"(p));
    return a;
}
__device__ __forceinline__ void ldm_x4(uint32_t* r, uint32_t addr) {
    asm volatile("ldmatrix.sync.aligned.m8n8.x4.shared.b16 {%0,%1,%2,%3}, [%4];"
        : "=r"(r[0]), "=r"(r[1]), "=r"(r[2]), "=r"(r[3]) : "r"(addr));
}
__device__ __forceinline__ void mma_bf16(float* c, const uint32_t* a, const uint32_t* b) {
    asm volatile("mma.sync.aligned.m16n8k16.row.col.f32.bf16.bf16.f32 "
        "{%0,%1,%2,%3}, {%4,%5,%6,%7}, {%8,%9}, {%0,%1,%2,%3};"
        : "+f"(c[0]), "+f"(c[1]), "+f"(c[2]), "+f"(c[3])
        : "r"(a[0]), "r"(a[1]), "r"(a[2]), "r"(a[3]), "r"(b[0]), "r"(b[1]));
}
#define CP16(dst, src) asm volatile("cp.async.cg.shared.global [%0], [%1], 16;" :: "r"(dst), "l"(src))
#define CP_COMMIT()    asm volatile("cp.async.commit_group;" ::: "memory")
#define CP_WAIT0()     asm volatile("cp.async.wait_group 0;" ::: "memory")
#define CP_WAIT1()     asm volatile("cp.async.wait_group 1;" ::: "memory")

__device__ __forceinline__ void split4(float4 a, uint2& h, uint2& l) {
    __nv_bfloat16 h0 = __float2bfloat16(a.x), h1 = __float2bfloat16(a.y);
    __nv_bfloat16 h2 = __float2bfloat16(a.z), h3 = __float2bfloat16(a.w);
    float l0 = a.x - __bfloat162float(h0), l1 = a.y - __bfloat162float(h1);
    float l2 = a.z - __bfloat162float(h2), l3 = a.w - __bfloat162float(h3);
    __nv_bfloat162 ph0{h0, h1}, ph1{h2, h3};
    __nv_bfloat162 pl0{__float2bfloat16(l0), __float2bfloat16(l1)};
    __nv_bfloat162 pl1{__float2bfloat16(l2), __float2bfloat16(l3)};
    h = make_uint2(*reinterpret_cast<uint32_t*>(&ph0), *reinterpret_cast<uint32_t*>(&ph1));
    l = make_uint2(*reinterpret_cast<uint32_t*>(&pl0), *reinterpret_cast<uint32_t*>(&pl1));
}

// ============================================================
// K0a: split q,k to bf16 hi/lo
// ============================================================
__global__ __launch_bounds__(256) void k_split_qk(
    const float* __restrict__ q, const float* __restrict__ kmat)
{
    const size_t i = ((size_t)blockIdx.x * 256 + threadIdx.x) * 4;
    uint2 h, l;
    split4(*reinterpret_cast<const float4*>(q + i), h, l);
    *reinterpret_cast<uint2*>(&g_qh[i]) = h;
    *reinterpret_cast<uint2*>(&g_ql[i]) = l;
    split4(*reinterpret_cast<const float4*>(kmat + i), h, l);
    *reinterpret_cast<uint2*>(&g_kh[i]) = h;
    *reinterpret_cast<uint2*>(&g_kl[i]) = l;
}

// K0b: v^T split  [b][d][j]
__global__ void k_split_v(const float* __restrict__ v)
{
    __shared__ float tile[32][33];
    const int b = blockIdx.z, j0 = blockIdx.x * 32, d0 = blockIdx.y * 32;
    const int tx = threadIdx.x, ty = threadIdx.y;
#pragma unroll
    for (int i = 0; i < 4; i++)
        tile[ty + i * 8][tx] = v[((size_t)b * L + j0 + ty + i * 8) * DV + d0 + tx];
    __syncthreads();
#pragma unroll
    for (int i = 0; i < 4; i++) {
        float x = tile[tx][ty + i * 8];
        __nv_bfloat16 h = __float2bfloat16(x);
        __nv_bfloat16 lo = __float2bfloat16(x - __bfloat162float(h));
        size_t idx = ((size_t)b * D + d0 + ty + i * 8) * L + j0 + tx;
        g_vTh[idx] = h;
        g_vTl[idx] = lo;
    }
}

// ============================================================
// K1: fused  E = mask*exp(q k^T)  + row/col partial sums.
// grid (4 jt4, 16 it, B), block 256.
// ============================================================
__global__ __launch_bounds__(256) void k_qkE(
    const float* __restrict__ Mg, float* __restrict__ E)
{
    extern __shared__ __align__(16) char smem[];
    __shared__ float colacc[4][512];   // [wr][col within 512-window]

    const int tid = threadIdx.x;
    const int w = tid >> 5, lane = tid & 31;
    const int b = blockIdx.z;
    const int i0 = blockIdx.y * 128;
    const int jt4 = blockIdx.x;

    const uint32_t bq  = smem_u32(smem);
    const uint32_t bql = bq + TILEB;
    const uint32_t bk[2]  = {bq + 2 * TILEB, bq + 4 * TILEB};
    const uint32_t bkl[2] = {bq + 3 * TILEB, bq + 5 * TILEB};

    const __nv_bfloat16* qh = g_qh + ((size_t)b * L + i0) * D;
    const __nv_bfloat16* ql = g_ql + ((size_t)b * L + i0) * D;

    // zero column accumulators
#pragma unroll
    for (int u = 0; u < 8; u++) ((float*)colacc)[u * 256 + tid] = 0.f;

    // issue q tiles + k tile 0
#pragma unroll
    for (int u = 0; u < 8; u++) {
        int f = u * 256 + tid;
        int row = f >> 4, c = f & 15;
        uint32_t so = (uint32_t)row * PITCHB + (uint32_t)c * 16;
        CP16(bq  + so, qh + (size_t)row * D + c * 8);
        CP16(bql + so, ql + (size_t)row * D + c * 8);
    }
    {
        const int j0 = jt4 * 512;
        const __nv_bfloat16* kh = g_kh + ((size_t)b * L + j0) * D;
        const __nv_bfloat16* kl = g_kl + ((size_t)b * L + j0) * D;
#pragma unroll
        for (int u = 0; u < 8; u++) {
            int f = u * 256 + tid;
            int row = f >> 4, c = f & 15;
            uint32_t so = (uint32_t)row * PITCHB + (uint32_t)c * 16;
            CP16(bk[0]  + so, kh + (size_t)row * D + c * 8);
            CP16(bkl[0] + so, kl + (size_t)row * D + c * 8);
        }
    }
    CP_COMMIT();

    const int wr = w & 3, wc = w >> 2;
    const int tr = lane >> 2, tc = lane & 3;
    float rowsum[4] = {0.f, 0.f, 0.f, 0.f};

    for (int jl = 0; jl < 4; jl++) {
        const int jt = jt4 * 4 + jl;
        const int j0 = jt * 128;
        if (jl < 3) {   // prefetch next k
            const int jn = j0 + 128;
            const __nv_bfloat16* kh = g_kh + ((size_t)b * L + jn) * D;
            const __nv_bfloat16* kl = g_kl + ((size_t)b * L + jn) * D;
            const uint32_t dh = bk[(jl + 1) & 1], dl = bkl[(jl + 1) & 1];
#pragma unroll
            for (int u = 0; u < 8; u++) {
                int f = u * 256 + tid;
                int row = f >> 4, c = f & 15;
                uint32_t so = (uint32_t)row * PITCHB + (uint32_t)c * 16;
                CP16(dh + so, kh + (size_t)row * D + c * 8);
                CP16(dl + so, kl + (size_t)row * D + c * 8);
            }
            CP_COMMIT();
            CP_WAIT1();
        } else {
            CP_WAIT0();
        }
        __syncthreads();

        float acc[2][8][4];
#pragma unroll
        for (int mt = 0; mt < 2; mt++)
#pragma unroll
            for (int nt = 0; nt < 8; nt++)
#pragma unroll
                for (int u = 0; u < 4; u++) acc[mt][nt][u] = 0.f;

        const uint32_t bkh = bk[jl & 1], bklo = bkl[jl & 1];
#pragma unroll
        for (int ks = 0; ks < 8; ks++) {
            const uint32_t kb0 = ks * 32;
            uint32_t Ah[2][4], Al[2][4], Bh[4][4], Bl[4][4];
            uint32_t arow = (uint32_t)(wr * 32 + (lane & 15)) * PITCHB + kb0 + ((lane >> 4) << 4);
#pragma unroll
            for (int mt = 0; mt < 2; mt++) {
                uint32_t ad = arow + mt * 16 * PITCHB;
                ldm_x4(Ah[mt], bq  + ad);
                ldm_x4(Al[mt], bql + ad);
            }
            uint32_t brow = (uint32_t)(wc * 64 + (lane & 7) + ((lane >> 4) << 3)) * PITCHB
                          + kb0 + (((lane >> 3) & 1) << 4);
#pragma unroll
            for (int ntp = 0; ntp < 4; ntp++) {
                uint32_t bd = brow + ntp * 16 * PITCHB;
                ldm_x4(Bh[ntp], bkh  + bd);
                ldm_x4(Bl[ntp], bklo + bd);
            }
#pragma unroll
            for (int mt = 0; mt < 2; mt++)
#pragma unroll
                for (int ntp = 0; ntp < 4; ntp++) {
                    mma_bf16(acc[mt][2 * ntp],     Ah[mt], &Bh[ntp][0]);
                    mma_bf16(acc[mt][2 * ntp + 1], Ah[mt], &Bh[ntp][2]);
                    mma_bf16(acc[mt][2 * ntp],     Al[mt], &Bh[ntp][0]);
                    mma_bf16(acc[mt][2 * ntp + 1], Al[mt], &Bh[ntp][2]);
                    mma_bf16(acc[mt][2 * ntp],     Ah[mt], &Bl[ntp][0]);
                    mma_bf16(acc[mt][2 * ntp + 1], Ah[mt], &Bl[ntp][2]);
                }
        }
        __syncthreads();   // ldmatrix done before next prefetch overwrites

        // ---- fused epilogue: E = mask*exp(S), row/col partial sums ----
        const float* Mb = Mg + ((size_t)b * L + i0) * L + j0;
        float*       Eb = E  + ((size_t)b * L + i0) * L + j0;
        float cs0[8], cs1[8];
#pragma unroll
        for (int nt = 0; nt < 8; nt++) { cs0[nt] = 0.f; cs1[nt] = 0.f; }

#pragma unroll
        for (int mt = 0; mt < 2; mt++)
#pragma unroll
            for (int nt = 0; nt < 8; nt++) {
                int r = wr * 32 + mt * 16 + tr;
                int cc = wc * 64 + nt * 8 + tc * 2;
                float2 mk0 = *reinterpret_cast<const float2*>(Mb + (size_t)r * L + cc);
                float2 mk1 = *reinterpret_cast<const float2*>(Mb + (size_t)(r + 8) * L + cc);
                float e0 = mk0.x * __expf(acc[mt][nt][0]);
                float e1 = mk0.y * __expf(acc[mt][nt][1]);
                float e2 = mk1.x * __expf(acc[mt][nt][2]);
                float e3 = mk1.y * __expf(acc[mt][nt][3]);
                *reinterpret_cast<float2*>(Eb + (size_t)r * L + cc)       = make_float2(e0, e1);
                *reinterpret_cast<float2*>(Eb + (size_t)(r + 8) * L + cc) = make_float2(e2, e3);
                rowsum[mt * 2]     += e0 + e1;
                rowsum[mt * 2 + 1] += e2 + e3;
                cs0[nt] += e0 + e2;
                cs1[nt] += e1 + e3;
            }
        // reduce col sums over tr (butterfly on lane bits 2..4)
#pragma unroll
        for (int nt = 0; nt < 8; nt++) {
            cs0[nt] += __shfl_xor_sync(0xFFFFFFFFu, cs0[nt], 4);
            cs0[nt] += __shfl_xor_sync(0xFFFFFFFFu, cs0[nt], 8);
            cs0[nt] += __shfl_xor_sync(0xFFFFFFFFu, cs0[nt], 16);
            cs1[nt] += __shfl_xor_sync(0xFFFFFFFFu, cs1[nt], 4);
            cs1[nt] += __shfl_xor_sync(0xFFFFFFFFu, cs1[nt], 8);
            cs1[nt] += __shfl_xor_sync(0xFFFFFFFFu, cs1[nt], 16);
        }
#pragma unroll
        for (int nt = 0; nt < 8; nt++) {
            if (tr == nt) {
                int c = jl * 128 + wc * 64 + nt * 8 + tc * 2;
                colacc[wr][c]     += cs0[nt];
                colacc[wr][c + 1] += cs1[nt];
            }
        }
    }

    // row partials (this warp's 256 cols across 4 jl)
#pragma unroll
    for (int u = 0; u < 4; u++) {
        rowsum[u] += __shfl_xor_sync(0xFFFFFFFFu, rowsum[u], 1);
        rowsum[u] += __shfl_xor_sync(0xFFFFFFFFu, rowsum[u], 2);
    }
    if (tc == 0) {
        float* rp = &g_rps[(size_t)(jt4 * 2 + wc) * BL + (size_t)b * L + i0 + wr * 32 + tr];
        rp[0] = rowsum[0]; rp[8] = rowsum[1]; rp[16] = rowsum[2]; rp[24] = rowsum[3];
    }

    // col partials
    __syncthreads();
    {
        int c = tid * 2;
        float s0 = colacc[0][c] + colacc[1][c] + colacc[2][c] + colacc[3][c];
        float s1 = colacc[0][c + 1] + colacc[1][c + 1] + colacc[2][c + 1] + colacc[3][c + 1];
        float* cp = &g_cps[(size_t)blockIdx.y * BL + (size_t)b * L + jt4 * 512 + c];
        cp[0] = s0; cp[1] = s1;
    }
}

// ============================================================
// K2: merge partials -> rdi, cdi
// ============================================================
__global__ __launch_bounds__(256) void k_merge()
{
    const int idx = blockIdx.x * 256 + threadIdx.x;
    float rs = 0.f;
#pragma unroll
    for (int p = 0; p < 8; p++) rs += g_rps[(size_t)p * BL + idx];
    g_rdi[idx] = 1.0f / (rs + EPSV);
    float cs = 0.f;
#pragma unroll
    for (int p = 0; p < 16; p++) cs += g_cps[(size_t)p * BL + idx];
    g_cdi[idx] = 1.0f / (cs + EPSV);
}

// ============================================================
// K5: gated = (E*rdi)*(E*cdi) in place + out partial = gated @ v (mma).
// grid (16 it, 2 ks, B), block 256.
// ============================================================
__global__ __launch_bounds__(256) void k_gate_out_mma(float* __restrict__ Eg)
{
    extern __shared__ __align__(16) char smem[];
    __shared__ float F_s[128];
    __shared__ float cd_s[128];

    const int tid = threadIdx.x;
    const int w = tid >> 5, lane = tid & 31;
    const int b = blockIdx.z;
    const int i0 = blockIdx.x * 128;
    const int ks = blockIdx.y;

    const uint32_t bg  = smem_u32(smem);
    const uint32_t bgl = bg + TILEB;
    const uint32_t bv[2]  = {bg + 2 * TILEB, bg + 4 * TILEB};
    const uint32_t bvl[2] = {bg + 3 * TILEB, bg + 5 * TILEB};

    if (tid < 128) F_s[tid] = g_rdi[(size_t)b * L + i0 + tid];

    const int wr = w & 3, wc = w >> 2;
    const int tr = lane >> 2, tc = lane & 3;
    float acc[2][8][4];
#pragma unroll
    for (int mt = 0; mt < 2; mt++)
#pragma unroll
        for (int nt = 0; nt < 8; nt++)
#pragma unroll
            for (int u = 0; u < 4; u++) acc[mt][nt][u] = 0.f;

    float* Eb = Eg + ((size_t)b * L + i0) * L;
    const __nv_bfloat16* vhB = g_vTh + (size_t)b * D * L;
    const __nv_bfloat16* vlB = g_vTl + (size_t)b * D * L;

    // prefetch v(jc=0)
    {
        const int j0 = ks * 1024;
#pragma unroll
        for (int u = 0; u < 8; u++) {
            int f = u * 256 + tid;
            int row = f >> 4, c = f & 15;
            uint32_t so = (uint32_t)row * PITCHB + (uint32_t)c * 16;
            CP16(bv[0]  + so, vhB + (size_t)row * L + j0 + c * 8);
            CP16(bvl[0] + so, vlB + (size_t)row * L + j0 + c * 8);
        }
        CP_COMMIT();
    }

    for (int jc = 0; jc < 8; jc++) {
        const int j0 = (ks * 8 + jc) * 128;
        if (tid < 32)
            *reinterpret_cast<float4*>(&cd_s[tid * 4]) =
                *reinterpret_cast<const float4*>(&g_cdi[(size_t)b * L + j0 + tid * 4]);
        if (jc < 7) {   // prefetch next v
            const int jn = j0 + 128;
            const uint32_t dh = bv[(jc + 1) & 1], dl = bvl[(jc + 1) & 1];
#pragma unroll
            for (int u = 0; u < 8; u++) {
                int f = u * 256 + tid;
                int row = f >> 4, c = f & 15;
                uint32_t so = (uint32_t)row * PITCHB + (uint32_t)c * 16;
                CP16(dh + so, vhB + (size_t)row * L + jn + c * 8);
                CP16(dl + so, vlB + (size_t)row * L + jn + c * 8);
            }
            CP_COMMIT();
        }
        __syncthreads();

        // gate: read E, write gated, split -> smem
#pragma unroll
        for (int it = 0; it < 16; it++) {
            int f = it * 256 + tid;
            int row = f >> 5, c4 = f & 31;
            size_t off = (size_t)row * L + j0 + c4 * 4;
            float4 e = *reinterpret_cast<const float4*>(Eb + off);
            float4 cd = *reinterpret_cast<const float4*>(&cd_s[c4 * 4]);
            float Fi = F_s[row];
            float4 g;
            g.x = (e.x * Fi) * (e.x * cd.x);
            g.y = (e.y * Fi) * (e.y * cd.y);
            g.z = (e.z * Fi) * (e.z * cd.z);
            g.w = (e.w * Fi) * (e.w * cd.w);
            *reinterpret_cast<float4*>(Eb + off) = g;
            uint2 h, l;
            split4(g, h, l);
            uint32_t so = (uint32_t)row * PITCHB + (uint32_t)c4 * 8;
            *reinterpret_cast<uint2*>(smem + so)         = h;
            *reinterpret_cast<uint2*>(smem + TILEB + so) = l;
        }
        if (jc < 7) CP_WAIT1(); else CP_WAIT0();
        __syncthreads();

        const uint32_t bvh = bv[jc & 1], bvlo = bvl[jc & 1];
#pragma unroll
        for (int kss = 0; kss < 8; kss++) {
            const uint32_t kb0 = kss * 32;
            uint32_t Ah[2][4], Al[2][4], Bh[4][4], Bl[4][4];
            uint32_t arow = (uint32_t)(wr * 32 + (lane & 15)) * PITCHB + kb0 + ((lane >> 4) << 4);
#pragma unroll
            for (int mt = 0; mt < 2; mt++) {
                uint32_t ad = arow + mt * 16 * PITCHB;
                ldm_x4(Ah[mt], bg  + ad);
                ldm_x4(Al[mt], bgl + ad);
            }
            uint32_t brow = (uint32_t)(wc * 64 + (lane & 7) + ((lane >> 4) << 3)) * PITCHB
                          + kb0 + (((lane >> 3) & 1) << 4);
#pragma unroll
            for (int ntp = 0; ntp < 4; ntp++) {
                uint32_t bd = brow + ntp * 16 * PITCHB;
                ldm_x4(Bh[ntp], bvh  + bd);
                ldm_x4(Bl[ntp], bvlo + bd);
            }
#pragma unroll
            for (int mt = 0; mt < 2; mt++)
#pragma unroll
                for (int ntp = 0; ntp < 4; ntp++) {
                    mma_bf16(acc[mt][2 * ntp],     Ah[mt], &Bh[ntp][0]);
                    mma_bf16(acc[mt][2 * ntp + 1], Ah[mt], &Bh[ntp][2]);
                    mma_bf16(acc[mt][2 * ntp],     Al[mt], &Bh[ntp][0]);
                    mma_bf16(acc[mt][2 * ntp + 1], Al[mt], &Bh[ntp][2]);
                    mma_bf16(acc[mt][2 * ntp],     Ah[mt], &Bl[ntp][0]);
                    mma_bf16(acc[mt][2 * ntp + 1], Ah[mt], &Bl[ntp][2]);
                }
        }
        __syncthreads();
    }

    // out partial: direct float2 stores
    float* op = g_opart + (((size_t)ks * BB + b) * L + i0) * DV;
#pragma unroll
    for (int mt = 0; mt < 2; mt++)
#pragma unroll
        for (int nt = 0; nt < 8; nt++) {
            int r = wr * 32 + mt * 16 + tr;
            int cc = wc * 64 + nt * 8 + tc * 2;
            *reinterpret_cast<float2*>(op + (size_t)r * DV + cc) =
                make_float2(acc[mt][nt][0], acc[mt][nt][1]);
            *reinterpret_cast<float2*>(op + (size_t)(r + 8) * DV + cc) =
                make_float2(acc[mt][nt][2], acc[mt][nt][3]);
        }
}

// K6: reduce 2 output partials
__global__ __launch_bounds__(256) void k_out_reduce(float* __restrict__ out)
{
    const size_t i = ((size_t)blockIdx.x * 256 + threadIdx.x) * 4;
    const size_t n = (size_t)BB * L * DV;
    float4 a = *reinterpret_cast<const float4*>(&g_opart[i]);
    float4 bq = *reinterpret_cast<const float4*>(&g_opart[n + i]);
    float4 r;
    r.x = a.x + bq.x; r.y = a.y + bq.y; r.z = a.z + bq.z; r.w = a.w + bq.w;
    *reinterpret_cast<float4*>(out + i) = r;
}

// ============================================================
extern "C" void kernel_launch(void* const* d_in, const int* in_sizes, int n_in,
                              void* d_out, int out_size)
{
    const float* q    = (const float*)d_in[0];
    const float* kmat = (const float*)d_in[1];
    const float* v    = (const float*)d_in[2];
    const float* mask = (const float*)d_in[3];

    float* out   = (float*)d_out;
    float* gated = out + (size_t)BB * L * DV;   // E -> gated in place

    cudaFuncSetAttribute(k_qkE,          cudaFuncAttributeMaxDynamicSharedMemorySize, SMEM6);
    cudaFuncSetAttribute(k_gate_out_mma, cudaFuncAttributeMaxDynamicSharedMemorySize, SMEM6);

    k_split_qk<<<(BB * L * D) / 1024, 256>>>(q, kmat);
    k_split_v<<<dim3(L / 32, D / 32, BB), dim3(32, 8)>>>(v);
    k_qkE<<<dim3(4, 16, BB), 256, SMEM6>>>(mask, gated);
    k_merge<<<BL / 256, 256>>>();
    k_gate_out_mma<<<dim3(16, 2, BB), 256, SMEM6>>>(gated);
    k_out_reduce<<<(BB * L * DV) / 1024, 256>>>(out);
}